// round 15
// baseline (speedup 1.0000x reference)
#include <cuda_runtime.h>
#include <cuda_bf16.h>
#include <math.h>

// Problem constants (fixed by the dataset)
#define B_   2
#define C_   64
#define E_   4
#define HLR_ 192
#define WLR_ 192
#define HHR_ 384
#define WHR_ 384
#define HWLR_ (HLR_*WLR_)
#define HWHR_ (HHR_*WHR_)

// Precomputed per-parity quantities (4 variants: hp*2+wp)
__device__ float g_wc[2][2][8][64];    // dynamic compress weights [hp][wp][j][c]
__device__ float g_we[2][2][64][8];    // dynamic expand weights   [hp][wp][c][j]
__device__ float g_offx[2][2], g_offy[2][2];   // raw offsets (fallback path)
__device__ int   g_fast[2];            // per-hp: fast window path valid
__device__ int   g_dyf[2];             // fast: shared y0 delta (rel. to byy)
__device__ int   g_dxmin[2];           // fast: window base delta (rel. to m)
__device__ int   g_ox[2][2];           // fast: per-q tap offset in window (0/1)
__device__ float g_wxf[2][2], g_wyf[2][2];     // fast: per-q fracs

// ---------------------------------------------------------------------------
// Kernel 0 (fast, from R7): 1 block x 1024 threads.
// ---------------------------------------------------------------------------
__global__ void __launch_bounds__(1024) precompute_kernel(
    const float* __restrict__ w1, const float* __restrict__ b1,
    const float* __restrict__ w2, const float* __restrict__ b2,
    const float* __restrict__ rw, const float* __restrict__ rb,
    const float* __restrict__ ow, const float* __restrict__ ob,
    const float* __restrict__ WC, const float* __restrict__ WE)
{
    __shared__ float s_e1[4][64];
    __shared__ float s_emb[4][64];
    __shared__ float s_rt[4][4];
    __shared__ float s_off[4][2];

    const int tid = threadIdx.x;

    if (tid < 256) {
        int v = tid >> 6, k = tid & 63;
        int hp = v >> 1, wp = v & 1;
        float ch = (hp + 0.5f) * 0.5f; ch = ch - floorf(ch + 0.001f) - 0.5f;
        float cw = (wp + 0.5f) * 0.5f; cw = cw - floorf(cw + 0.001f) - 0.5f;
        float4 wv = ((const float4*)w1)[k];
        float e1 = b1[k] + wv.x * 0.5f + wv.y * 0.5f + wv.z * ch + wv.w * cw;
        s_e1[v][k] = fmaxf(e1, 0.0f);
    }
    __syncthreads();

    {
        int v = tid >> 8, o = (tid >> 2) & 63, part = tid & 3;
        const float4* w2v = (const float4*)(w2 + o * 64 + part * 16);
        const float*  e1p = &s_e1[v][part * 16];
        float acc = 0.0f;
        #pragma unroll
        for (int t = 0; t < 4; t++) {
            float4 wv = w2v[t];
            acc += wv.x * e1p[t*4+0] + wv.y * e1p[t*4+1]
                 + wv.z * e1p[t*4+2] + wv.w * e1p[t*4+3];
        }
        acc += __shfl_xor_sync(0xFFFFFFFFu, acc, 1);
        acc += __shfl_xor_sync(0xFFFFFFFFu, acc, 2);
        if (part == 0) s_emb[v][o] = fmaxf(acc + b2[o], 0.0f);
    }
    __syncthreads();

    if (tid < 64) {
        int v = tid >> 4, e = (tid >> 2) & 3, part = tid & 3;
        const float4* rwv = (const float4*)(rw + e * 64 + part * 16);
        const float*  emp = &s_emb[v][part * 16];
        float acc = 0.0f;
        #pragma unroll
        for (int t = 0; t < 4; t++) {
            float4 wv = rwv[t];
            acc += wv.x * emp[t*4+0] + wv.y * emp[t*4+1]
                 + wv.z * emp[t*4+2] + wv.w * emp[t*4+3];
        }
        acc += __shfl_xor_sync(0xFFFFFFFFu, acc, 1);
        acc += __shfl_xor_sync(0xFFFFFFFFu, acc, 2);
        if (part == 0) s_rt[v][e] = 1.0f / (1.0f + expf(-(acc + rb[e])));
    } else if (tid < 96) {
        int idx = tid - 64;
        int v = idx >> 3, k = (idx >> 2) & 1, part = idx & 3;
        const float4* owv = (const float4*)(ow + k * 64 + part * 16);
        const float*  emp = &s_emb[v][part * 16];
        float acc = 0.0f;
        #pragma unroll
        for (int t = 0; t < 4; t++) {
            float4 wv = owv[t];
            acc += wv.x * emp[t*4+0] + wv.y * emp[t*4+1]
                 + wv.z * emp[t*4+2] + wv.w * emp[t*4+3];
        }
        acc += __shfl_xor_sync(0xFFFFFFFFu, acc, 1);
        acc += __shfl_xor_sync(0xFFFFFFFFu, acc, 2);
        if (part == 0) s_off[v][k] = acc + ob[k];
    }
    __syncthreads();

    if (tid < 2) {
        int hpp = tid;
        float ox0 = s_off[hpp*2 + 0][0], oy0 = s_off[hpp*2 + 0][1];
        float ox1 = s_off[hpp*2 + 1][0], oy1 = s_off[hpp*2 + 1][1];
        g_offx[hpp][0] = ox0; g_offx[hpp][1] = ox1;
        g_offy[hpp][0] = oy0; g_offy[hpp][1] = oy1;
        float tx0 = -0.25f + ox0;
        float tx1 =  0.25f + ox1;
        float tyb = (hpp + 0.5f) * 0.5f - 0.5f;
        float ty0 = tyb + oy0;
        float ty1 = tyb + oy1;
        float fx0 = floorf(tx0), fx1 = floorf(tx1);
        float fy0 = floorf(ty0), fy1 = floorf(ty1);
        int dx0 = (int)fx0, dx1 = (int)fx1;
        int dy0 = (int)fy0, dy1 = (int)fy1;
        g_fast[hpp] = (dy0 == dy1) && (abs(dx1 - dx0) <= 1);
        int dmn = min(dx0, dx1);
        g_dyf[hpp]   = dy0;
        g_dxmin[hpp] = dmn;
        g_ox[hpp][0] = dx0 - dmn;
        g_ox[hpp][1] = dx1 - dmn;
        g_wxf[hpp][0] = tx0 - fx0;  g_wxf[hpp][1] = tx1 - fx1;
        g_wyf[hpp][0] = ty0 - fy0;  g_wyf[hpp][1] = ty1 - fy1;
    }
    __syncthreads();

    {
        if (tid < 512) {
            int v = tid >> 7, r4 = tid & 127;
            float r0 = s_rt[v][0], r1 = s_rt[v][1], r2 = s_rt[v][2], r3 = s_rt[v][3];
            const float4* wc4 = (const float4*)WC;
            float4 a0 = wc4[0*128 + r4], a1 = wc4[1*128 + r4];
            float4 a2 = wc4[2*128 + r4], a3 = wc4[3*128 + r4];
            float4 o4;
            o4.x = r0*a0.x + r1*a1.x + r2*a2.x + r3*a3.x;
            o4.y = r0*a0.y + r1*a1.y + r2*a2.y + r3*a3.y;
            o4.z = r0*a0.z + r1*a1.z + r2*a2.z + r3*a3.z;
            o4.w = r0*a0.w + r1*a1.w + r2*a2.w + r3*a3.w;
            ((float4*)&g_wc[0][0][0][0])[v * 128 + r4] = o4;
        } else {
            int t = tid - 512;
            int v = t >> 7, r4 = t & 127;
            float r0 = s_rt[v][0], r1 = s_rt[v][1], r2 = s_rt[v][2], r3 = s_rt[v][3];
            const float4* we4 = (const float4*)WE;
            float4 a0 = we4[0*128 + r4], a1 = we4[1*128 + r4];
            float4 a2 = we4[2*128 + r4], a3 = we4[3*128 + r4];
            float4 o4;
            o4.x = r0*a0.x + r1*a1.x + r2*a2.x + r3*a3.x;
            o4.y = r0*a0.y + r1*a1.y + r2*a2.y + r3*a3.y;
            o4.z = r0*a0.z + r1*a1.z + r2*a2.z + r3*a3.z;
            o4.w = r0*a0.w + r1*a1.w + r2*a2.w + r3*a3.w;
            ((float4*)&g_we[0][0][0][0])[v * 128 + r4] = o4;
        }
    }
}

// ---------------------------------------------------------------------------
// Main kernel (R14 structure + shuffle-dedup gathers).
// Block = 256 threads = 8 warps; warp = channel group g, lane l = LR column.
// Fast path per channel-row: ONE warp-wide LDG (k=l) + 4-lane edge LDG
// (k=32,33 for both rows) + shfl_down for k=l+1, l+2. 6 wf/channel vs 12.
// grid = (WHR/64, HHR, B); 4 blocks/SM.
// ---------------------------------------------------------------------------
__global__ void __launch_bounds__(256, 4) upsample_main(
    const float* __restrict__ fused, float* __restrict__ out)
{
    __shared__ float  s_wc[2][8][64];       // [q][j][c]
    __shared__ float  s_we[2][64][8];       // [q][c][j]
    __shared__ float2 s_part[8][8][32];     // [j][g][m] packed (q0,q1)
    __shared__ float2 s_midf[8][32];        // [j][m]    packed (q0,q1)

    const int tid  = threadIdx.x;
    const int l    = tid & 31;
    const int g    = tid >> 5;               // warp index == channel group
    const int h    = blockIdx.y;
    const int hp   = h & 1;
    const int byy  = h >> 1;
    const int b    = blockIdx.z;
    const int mbase = blockIdx.x * 32;
    const int m    = mbase + l;               // LR column

    const float* basep = fused + (size_t)(b * C_ + g * 8) * HWLR_;

    float fea[2][8];

    if (g_fast[hp]) {
        const int y0 = byy + g_dyf[hp];
        const bool yv0 = (y0 >= 0) && (y0 < HLR_);
        const bool yv1 = (y0 + 1 >= 0) && (y0 + 1 < HLR_);
        const int yc0 = min(max(y0, 0), HLR_ - 1);
        const int yc1 = min(max(y0 + 1, 0), HLR_ - 1);
        const float wx0 = g_wxf[hp][0], wx1 = g_wxf[hp][1];
        const float wy0 = g_wyf[hp][0], wy1 = g_wyf[hp][1];
        const int o0 = g_ox[hp][0], o1 = g_ox[hp][1];

        const int base = mbase + g_dxmin[hp];       // warp-uniform window base
        // per-lane main position k = l
        const int xl   = base + l;
        const bool xvl = (xl >= 0) && (xl < WLR_);
        const int xcl  = min(max(xl, 0), WLR_ - 1);
        // warp-uniform edge positions k = 32, 33
        const bool xv32 = (base + 32 >= 0) && (base + 32 < WLR_);
        const bool xv33 = (base + 33 >= 0) && (base + 33 < WLR_);
        const int xc32 = min(max(base + 32, 0), WLR_ - 1);
        const int xc33 = min(max(base + 33, 0), WLR_ - 1);
        // this lane's edge role: lanes 0,1 -> row0 k=32,33; lanes 2,3 -> row1
        const bool e_row1 = (l >= 2);
        const bool e_k33  = (l & 1);
        const bool e_yok  = e_row1 ? yv1 : yv0;
        const bool e_xok  = e_k33 ? xv33 : xv32;
        const int  e_off  = (e_row1 ? yc1 : yc0) * WLR_ + (e_k33 ? xc33 : xc32);
        const bool e_do   = (l < 4) && e_yok && e_xok;

        #pragma unroll
        for (int i = 0; i < 8; i++) {
            const float* pl = basep + (size_t)i * HWLR_;
            const float* r0 = pl + yc0 * WLR_;
            const float* r1 = pl + yc1 * WLR_;
            // main loads: window position k = l
            float v0 = (yv0 && xvl) ? r0[xcl] : 0.0f;
            float v1 = (yv1 && xvl) ? r1[xcl] : 0.0f;
            // edge load: lanes 0..3 fetch k=32,33 for both rows
            float ve = e_do ? pl[e_off] : 0.0f;
            // shifted copies via shuffle (validity already folded into v/ve)
            float t01 = __shfl_down_sync(0xFFFFFFFFu, v0, 1);
            float t02 = __shfl_down_sync(0xFFFFFFFFu, v0, 2);
            float t11 = __shfl_down_sync(0xFFFFFFFFu, v1, 1);
            float t12 = __shfl_down_sync(0xFFFFFFFFu, v1, 2);
            float e00 = __shfl_sync(0xFFFFFFFFu, ve, 0);
            float e01 = __shfl_sync(0xFFFFFFFFu, ve, 1);
            float e10 = __shfl_sync(0xFFFFFFFFu, ve, 2);
            float e11 = __shfl_sync(0xFFFFFFFFu, ve, 3);
            float u0 = v0;
            float u1 = (l == 31) ? e00 : t01;
            float u2 = (l == 30) ? e00 : ((l == 31) ? e01 : t02);
            float w0 = v1;
            float w1 = (l == 31) ? e10 : t11;
            float w2 = (l == 30) ? e10 : ((l == 31) ? e11 : t12);
            // taps
            {
                float a = o0 ? u1 : u0, bb = o0 ? u2 : u1;
                float c = o0 ? w1 : w0, d  = o0 ? w2 : w1;
                float top = a + wx0 * (bb - a);
                float bot = c + wx0 * (d - c);
                fea[0][i] = top + wy0 * (bot - top);
            }
            {
                float a = o1 ? u1 : u0, bb = o1 ? u2 : u1;
                float c = o1 ? w1 : w0, d  = o1 ? w2 : w1;
                float top = a + wx1 * (bb - a);
                float bot = c + wx1 * (d - c);
                fea[1][i] = top + wy1 * (bot - top);
            }
        }
    } else {
        #pragma unroll
        for (int q = 0; q < 2; q++) {
            float px = (float)m + (q + 0.5f) * 0.5f - 0.5f + g_offx[hp][q];
            float py = (float)byy + (hp + 0.5f) * 0.5f - 0.5f + g_offy[hp][q];
            float x0f = floorf(px), y0f = floorf(py);
            float wx = px - x0f, wy = py - y0f;
            int x0 = (int)x0f, y0 = (int)y0f;
            bool vx0 = (x0 >= 0) && (x0 < WLR_);
            bool vx1 = (x0 + 1 >= 0) && (x0 + 1 < WLR_);
            bool vy0 = (y0 >= 0) && (y0 < HLR_);
            bool vy1 = (y0 + 1 >= 0) && (y0 + 1 < HLR_);
            float w00 = (vy0 && vx0) ? (1.0f - wx) * (1.0f - wy) : 0.0f;
            float w01 = (vy0 && vx1) ? wx * (1.0f - wy)          : 0.0f;
            float w10 = (vy1 && vx0) ? (1.0f - wx) * wy          : 0.0f;
            float w11 = (vy1 && vx1) ? wx * wy                   : 0.0f;
            int xc0 = min(max(x0, 0), WLR_ - 1);
            int xc1 = min(max(x0 + 1, 0), WLR_ - 1);
            int yc0 = min(max(y0, 0), HLR_ - 1);
            int yc1 = min(max(y0 + 1, 0), HLR_ - 1);
            #pragma unroll
            for (int i = 0; i < 8; i++) {
                const float* pl = basep + (size_t)i * HWLR_;
                const float* r0 = pl + yc0 * WLR_;
                const float* r1 = pl + yc1 * WLR_;
                fea[q][i] = r0[xc0] * w00 + r0[xc1] * w01
                          + r1[xc0] * w10 + r1[xc1] * w11;
            }
        }
    }

    // ---- Stage dynamic weights (fills gather-latency shadow) -------------
    {
        const float4* srcc = (const float4*)&g_wc[hp][0][0][0];   // 256 f4
        const float4* srce = (const float4*)&g_we[hp][0][0][0];   // 256 f4
        ((float4*)&s_wc[0][0][0])[tid] = srcc[tid];
        ((float4*)&s_we[0][0][0])[tid] = srce[tid];
    }
    __syncthreads();

    // ---- Compress (8x8 matvec), both parities packed as float2 ----------
    {
        const float4* wc40 = (const float4*)&s_wc[0][0][g * 8];  // stride 16 f4
        const float4* wc41 = (const float4*)&s_wc[1][0][g * 8];
        float4 fa0 = make_float4(fea[0][0], fea[0][1], fea[0][2], fea[0][3]);
        float4 fb0 = make_float4(fea[0][4], fea[0][5], fea[0][6], fea[0][7]);
        float4 fa1 = make_float4(fea[1][0], fea[1][1], fea[1][2], fea[1][3]);
        float4 fb1 = make_float4(fea[1][4], fea[1][5], fea[1][6], fea[1][7]);
        #pragma unroll
        for (int j = 0; j < 8; j++) {
            float4 wa0 = wc40[j * 16], wb0 = wc40[j * 16 + 1];
            float4 wa1 = wc41[j * 16], wb1 = wc41[j * 16 + 1];
            float a0 = wa0.x * fa0.x + wa0.y * fa0.y + wa0.z * fa0.z + wa0.w * fa0.w
                     + wb0.x * fb0.x + wb0.y * fb0.y + wb0.z * fb0.z + wb0.w * fb0.w;
            float a1 = wa1.x * fa1.x + wa1.y * fa1.y + wa1.z * fa1.z + wa1.w * fa1.w
                     + wb1.x * fb1.x + wb1.y * fb1.y + wb1.z * fb1.z + wb1.w * fb1.w;
            s_part[j][g][l] = make_float2(a0, a1);
        }
    }
    __syncthreads();

    // ---- Reduce partials over channel groups: warp j -> midf[j][*] -------
    {
        const int j = g;
        float sx = 0.0f, sy = 0.0f;
        #pragma unroll
        for (int gg = 0; gg < 8; gg++) {
            float2 p = s_part[j][gg][l];
            sx += p.x; sy += p.y;
        }
        s_midf[j][l] = make_float2(sx, sy);
    }
    __syncthreads();

    // ---- Expand + residual + contiguous float2 stores -------------------
    float mid0[8], mid1[8];
    #pragma unroll
    for (int j = 0; j < 8; j++) {
        float2 mv = s_midf[j][l];
        mid0[j] = mv.x;
        mid1[j] = mv.y;
    }
    float* obp = out + ((size_t)(b * C_ + g * 8) * HHR_ + h) * WHR_ + 2 * m;
    #pragma unroll
    for (int i = 0; i < 8; i++) {
        const float4* we0 = (const float4*)&s_we[0][g * 8 + i][0];
        const float4* we1 = (const float4*)&s_we[1][g * 8 + i][0];
        float4 ea0 = we0[0], eb0 = we0[1];
        float4 ea1 = we1[0], eb1 = we1[1];
        float r0 = fea[0][i]
                 + ea0.x * mid0[0] + ea0.y * mid0[1] + ea0.z * mid0[2] + ea0.w * mid0[3]
                 + eb0.x * mid0[4] + eb0.y * mid0[5] + eb0.z * mid0[6] + eb0.w * mid0[7];
        float r1 = fea[1][i]
                 + ea1.x * mid1[0] + ea1.y * mid1[1] + ea1.z * mid1[2] + ea1.w * mid1[3]
                 + eb1.x * mid1[4] + eb1.y * mid1[5] + eb1.z * mid1[6] + eb1.w * mid1[7];
        float2 rv = make_float2(r0, r1);
        *(float2*)(obp + (size_t)i * HWHR_) = rv;
    }
}

// ---------------------------------------------------------------------------
extern "C" void kernel_launch(void* const* d_in, const int* in_sizes, int n_in,
                              void* d_out, int out_size)
{
    const float* fused = (const float*)d_in[1];
    const float* WC    = (const float*)d_in[2];
    const float* WE    = (const float*)d_in[3];
    const float* w1    = (const float*)d_in[4];
    const float* b1    = (const float*)d_in[5];
    const float* w2    = (const float*)d_in[6];
    const float* b2    = (const float*)d_in[7];
    const float* rw    = (const float*)d_in[8];
    const float* rb    = (const float*)d_in[9];
    const float* ow    = (const float*)d_in[10];
    const float* obv   = (const float*)d_in[11];
    float* out = (float*)d_out;

    precompute_kernel<<<1, 1024>>>(w1, b1, w2, b2, rw, rb, ow, obv, WC, WE);

    dim3 grid(WHR_ / 64, HHR_, B_);
    upsample_main<<<grid, 256>>>(fused, out);
}

// round 16
// speedup vs baseline: 1.0439x; 1.0439x over previous
#include <cuda_runtime.h>
#include <cuda_bf16.h>
#include <math.h>

// Problem constants (fixed by the dataset)
#define B_   2
#define C_   64
#define E_   4
#define HLR_ 192
#define WLR_ 192
#define HHR_ 384
#define WHR_ 384
#define HWLR_ (HLR_*WLR_)
#define HWHR_ (HHR_*WHR_)

// Precomputed per-parity quantities (4 variants: hp*2+wp)
__device__ float g_wc[2][2][8][64];    // dynamic compress weights [hp][wp][j][c]
__device__ float g_we[2][2][64][8];    // dynamic expand weights   [hp][wp][c][j]
__device__ float g_offx[2][2], g_offy[2][2];   // raw offsets (fallback path)
__device__ int   g_fast[2];            // per-hp: fast window path valid
__device__ int   g_dyf[2];             // fast: shared y0 delta (rel. to byy)
__device__ int   g_dxmin[2];           // fast: window base delta (rel. to m)
__device__ int   g_ox[2][2];           // fast: per-q tap offset in window (0/1)
__device__ float g_wxf[2][2], g_wyf[2][2];     // fast: per-q fracs

// ---------------------------------------------------------------------------
// Kernel 0 (fast, from R7): 1 block x 1024 threads.
// ---------------------------------------------------------------------------
__global__ void __launch_bounds__(1024) precompute_kernel(
    const float* __restrict__ w1, const float* __restrict__ b1,
    const float* __restrict__ w2, const float* __restrict__ b2,
    const float* __restrict__ rw, const float* __restrict__ rb,
    const float* __restrict__ ow, const float* __restrict__ ob,
    const float* __restrict__ WC, const float* __restrict__ WE)
{
    __shared__ float s_e1[4][64];
    __shared__ float s_emb[4][64];
    __shared__ float s_rt[4][4];
    __shared__ float s_off[4][2];

    const int tid = threadIdx.x;

    if (tid < 256) {
        int v = tid >> 6, k = tid & 63;
        int hp = v >> 1, wp = v & 1;
        float ch = (hp + 0.5f) * 0.5f; ch = ch - floorf(ch + 0.001f) - 0.5f;
        float cw = (wp + 0.5f) * 0.5f; cw = cw - floorf(cw + 0.001f) - 0.5f;
        float4 wv = ((const float4*)w1)[k];
        float e1 = b1[k] + wv.x * 0.5f + wv.y * 0.5f + wv.z * ch + wv.w * cw;
        s_e1[v][k] = fmaxf(e1, 0.0f);
    }
    __syncthreads();

    {
        int v = tid >> 8, o = (tid >> 2) & 63, part = tid & 3;
        const float4* w2v = (const float4*)(w2 + o * 64 + part * 16);
        const float*  e1p = &s_e1[v][part * 16];
        float acc = 0.0f;
        #pragma unroll
        for (int t = 0; t < 4; t++) {
            float4 wv = w2v[t];
            acc += wv.x * e1p[t*4+0] + wv.y * e1p[t*4+1]
                 + wv.z * e1p[t*4+2] + wv.w * e1p[t*4+3];
        }
        acc += __shfl_xor_sync(0xFFFFFFFFu, acc, 1);
        acc += __shfl_xor_sync(0xFFFFFFFFu, acc, 2);
        if (part == 0) s_emb[v][o] = fmaxf(acc + b2[o], 0.0f);
    }
    __syncthreads();

    if (tid < 64) {
        int v = tid >> 4, e = (tid >> 2) & 3, part = tid & 3;
        const float4* rwv = (const float4*)(rw + e * 64 + part * 16);
        const float*  emp = &s_emb[v][part * 16];
        float acc = 0.0f;
        #pragma unroll
        for (int t = 0; t < 4; t++) {
            float4 wv = rwv[t];
            acc += wv.x * emp[t*4+0] + wv.y * emp[t*4+1]
                 + wv.z * emp[t*4+2] + wv.w * emp[t*4+3];
        }
        acc += __shfl_xor_sync(0xFFFFFFFFu, acc, 1);
        acc += __shfl_xor_sync(0xFFFFFFFFu, acc, 2);
        if (part == 0) s_rt[v][e] = 1.0f / (1.0f + expf(-(acc + rb[e])));
    } else if (tid < 96) {
        int idx = tid - 64;
        int v = idx >> 3, k = (idx >> 2) & 1, part = idx & 3;
        const float4* owv = (const float4*)(ow + k * 64 + part * 16);
        const float*  emp = &s_emb[v][part * 16];
        float acc = 0.0f;
        #pragma unroll
        for (int t = 0; t < 4; t++) {
            float4 wv = owv[t];
            acc += wv.x * emp[t*4+0] + wv.y * emp[t*4+1]
                 + wv.z * emp[t*4+2] + wv.w * emp[t*4+3];
        }
        acc += __shfl_xor_sync(0xFFFFFFFFu, acc, 1);
        acc += __shfl_xor_sync(0xFFFFFFFFu, acc, 2);
        if (part == 0) s_off[v][k] = acc + ob[k];
    }
    __syncthreads();

    if (tid < 2) {
        int hpp = tid;
        float ox0 = s_off[hpp*2 + 0][0], oy0 = s_off[hpp*2 + 0][1];
        float ox1 = s_off[hpp*2 + 1][0], oy1 = s_off[hpp*2 + 1][1];
        g_offx[hpp][0] = ox0; g_offx[hpp][1] = ox1;
        g_offy[hpp][0] = oy0; g_offy[hpp][1] = oy1;
        float tx0 = -0.25f + ox0;
        float tx1 =  0.25f + ox1;
        float tyb = (hpp + 0.5f) * 0.5f - 0.5f;
        float ty0 = tyb + oy0;
        float ty1 = tyb + oy1;
        float fx0 = floorf(tx0), fx1 = floorf(tx1);
        float fy0 = floorf(ty0), fy1 = floorf(ty1);
        int dx0 = (int)fx0, dx1 = (int)fx1;
        int dy0 = (int)fy0, dy1 = (int)fy1;
        g_fast[hpp] = (dy0 == dy1) && (abs(dx1 - dx0) <= 1);
        int dmn = min(dx0, dx1);
        g_dyf[hpp]   = dy0;
        g_dxmin[hpp] = dmn;
        g_ox[hpp][0] = dx0 - dmn;
        g_ox[hpp][1] = dx1 - dmn;
        g_wxf[hpp][0] = tx0 - fx0;  g_wxf[hpp][1] = tx1 - fx1;
        g_wyf[hpp][0] = ty0 - fy0;  g_wyf[hpp][1] = ty1 - fy1;
    }
    __syncthreads();

    {
        if (tid < 512) {
            int v = tid >> 7, r4 = tid & 127;
            float r0 = s_rt[v][0], r1 = s_rt[v][1], r2 = s_rt[v][2], r3 = s_rt[v][3];
            const float4* wc4 = (const float4*)WC;
            float4 a0 = wc4[0*128 + r4], a1 = wc4[1*128 + r4];
            float4 a2 = wc4[2*128 + r4], a3 = wc4[3*128 + r4];
            float4 o4;
            o4.x = r0*a0.x + r1*a1.x + r2*a2.x + r3*a3.x;
            o4.y = r0*a0.y + r1*a1.y + r2*a2.y + r3*a3.y;
            o4.z = r0*a0.z + r1*a1.z + r2*a2.z + r3*a3.z;
            o4.w = r0*a0.w + r1*a1.w + r2*a2.w + r3*a3.w;
            ((float4*)&g_wc[0][0][0][0])[v * 128 + r4] = o4;
        } else {
            int t = tid - 512;
            int v = t >> 7, r4 = t & 127;
            float r0 = s_rt[v][0], r1 = s_rt[v][1], r2 = s_rt[v][2], r3 = s_rt[v][3];
            const float4* we4 = (const float4*)WE;
            float4 a0 = we4[0*128 + r4], a1 = we4[1*128 + r4];
            float4 a2 = we4[2*128 + r4], a3 = we4[3*128 + r4];
            float4 o4;
            o4.x = r0*a0.x + r1*a1.x + r2*a2.x + r3*a3.x;
            o4.y = r0*a0.y + r1*a1.y + r2*a2.y + r3*a3.y;
            o4.z = r0*a0.z + r1*a1.z + r2*a2.z + r3*a3.z;
            o4.w = r0*a0.w + r1*a1.w + r2*a2.w + r3*a3.w;
            ((float4*)&g_we[0][0][0][0])[v * 128 + r4] = o4;
        }
    }
}

// ---------------------------------------------------------------------------
// Main kernel (R14 structure + aligned-float2 window gathers).
// Block = 256 threads = 8 warps; warp = channel group g, lane l = LR column.
// Fast path per channel-row: taps x, x+1, x+2 all lie in the 4-float window
// at a = x & ~1, fetched by TWO aligned LDG.64 (clamped addresses; validity
// masks zero OOB taps). 4 LDG.64/channel vs 6 misaligned LDG.32.
// grid = (WHR/64, HHR, B); 4 blocks/SM.
// ---------------------------------------------------------------------------
__global__ void __launch_bounds__(256, 4) upsample_main(
    const float* __restrict__ fused, float* __restrict__ out)
{
    __shared__ float  s_wc[2][8][64];       // [q][j][c]
    __shared__ float  s_we[2][64][8];       // [q][c][j]
    __shared__ float2 s_part[8][8][32];     // [j][g][m] packed (q0,q1)
    __shared__ float2 s_midf[8][32];        // [j][m]    packed (q0,q1)

    const int tid  = threadIdx.x;
    const int l    = tid & 31;
    const int g    = tid >> 5;               // warp index == channel group
    const int h    = blockIdx.y;
    const int hp   = h & 1;
    const int byy  = h >> 1;
    const int b    = blockIdx.z;
    const int mbase = blockIdx.x * 32;
    const int m    = mbase + l;               // LR column

    const float* basep = fused + (size_t)(b * C_ + g * 8) * HWLR_;

    float fea[2][8];

    if (g_fast[hp]) {
        const int y0 = byy + g_dyf[hp];
        const bool yv0 = (y0 >= 0) && (y0 < HLR_);
        const bool yv1 = (y0 + 1 >= 0) && (y0 + 1 < HLR_);
        const int yc0 = min(max(y0, 0), HLR_ - 1);
        const int yc1 = min(max(y0 + 1, 0), HLR_ - 1);
        const float wx0 = g_wxf[hp][0], wx1 = g_wxf[hp][1];
        const float wy0 = g_wyf[hp][0], wy1 = g_wyf[hp][1];
        const int o0 = g_ox[hp][0], o1 = g_ox[hp][1];

        // taps at x, x+1, x+2; all inside aligned 4-float window at a = x & ~1
        const int x  = mbase + g_dxmin[hp] + l;
        const int s  = x & 1;
        const int a  = x - s;                          // even
        const int ca  = min(max(a, 0), WLR_ - 2);      // clamped, even
        const int ca2 = min(max(a + 2, 0), WLR_ - 2);  // clamped, even
        const bool xv0 = (x >= 0) && (x < WLR_);
        const bool xv1 = (x + 1 >= 0) && (x + 1 < WLR_);
        const bool xv2 = (x + 2 >= 0) && (x + 2 < WLR_);
        const bool m00 = yv0 && xv0, m01 = yv0 && xv1, m02 = yv0 && xv2;
        const bool m10 = yv1 && xv0, m11 = yv1 && xv1, m12 = yv1 && xv2;

        #pragma unroll
        for (int i = 0; i < 8; i++) {
            const float* pl = basep + (size_t)i * HWLR_;
            const float* r0 = pl + yc0 * WLR_;
            const float* r1 = pl + yc1 * WLR_;
            float2 A0 = *(const float2*)(r0 + ca);
            float2 B0 = *(const float2*)(r0 + ca2);
            float2 A1 = *(const float2*)(r1 + ca);
            float2 B1 = *(const float2*)(r1 + ca2);
            // window values at offsets s, s+1, s+2 (s in {0,1})
            float u0 = s ? A0.y : A0.x;
            float u1 = s ? B0.x : A0.y;
            float u2 = s ? B0.y : B0.x;
            float w0 = s ? A1.y : A1.x;
            float w1 = s ? B1.x : A1.y;
            float w2 = s ? B1.y : B1.x;
            u0 = m00 ? u0 : 0.0f;  u1 = m01 ? u1 : 0.0f;  u2 = m02 ? u2 : 0.0f;
            w0 = m10 ? w0 : 0.0f;  w1 = m11 ? w1 : 0.0f;  w2 = m12 ? w2 : 0.0f;
            {
                float aa = o0 ? u1 : u0, bb = o0 ? u2 : u1;
                float cc = o0 ? w1 : w0, dd = o0 ? w2 : w1;
                float top = aa + wx0 * (bb - aa);
                float bot = cc + wx0 * (dd - cc);
                fea[0][i] = top + wy0 * (bot - top);
            }
            {
                float aa = o1 ? u1 : u0, bb = o1 ? u2 : u1;
                float cc = o1 ? w1 : w0, dd = o1 ? w2 : w1;
                float top = aa + wx1 * (bb - aa);
                float bot = cc + wx1 * (dd - cc);
                fea[1][i] = top + wy1 * (bot - top);
            }
        }
    } else {
        #pragma unroll
        for (int q = 0; q < 2; q++) {
            float px = (float)m + (q + 0.5f) * 0.5f - 0.5f + g_offx[hp][q];
            float py = (float)byy + (hp + 0.5f) * 0.5f - 0.5f + g_offy[hp][q];
            float x0f = floorf(px), y0f = floorf(py);
            float wx = px - x0f, wy = py - y0f;
            int x0 = (int)x0f, y0 = (int)y0f;
            bool vx0 = (x0 >= 0) && (x0 < WLR_);
            bool vx1 = (x0 + 1 >= 0) && (x0 + 1 < WLR_);
            bool vy0 = (y0 >= 0) && (y0 < HLR_);
            bool vy1 = (y0 + 1 >= 0) && (y0 + 1 < HLR_);
            float w00 = (vy0 && vx0) ? (1.0f - wx) * (1.0f - wy) : 0.0f;
            float w01 = (vy0 && vx1) ? wx * (1.0f - wy)          : 0.0f;
            float w10 = (vy1 && vx0) ? (1.0f - wx) * wy          : 0.0f;
            float w11 = (vy1 && vx1) ? wx * wy                   : 0.0f;
            int xc0 = min(max(x0, 0), WLR_ - 1);
            int xc1 = min(max(x0 + 1, 0), WLR_ - 1);
            int yc0 = min(max(y0, 0), HLR_ - 1);
            int yc1 = min(max(y0 + 1, 0), HLR_ - 1);
            #pragma unroll
            for (int i = 0; i < 8; i++) {
                const float* pl = basep + (size_t)i * HWLR_;
                const float* r0 = pl + yc0 * WLR_;
                const float* r1 = pl + yc1 * WLR_;
                fea[q][i] = r0[xc0] * w00 + r0[xc1] * w01
                          + r1[xc0] * w10 + r1[xc1] * w11;
            }
        }
    }

    // ---- Stage dynamic weights (fills gather-latency shadow) -------------
    {
        const float4* srcc = (const float4*)&g_wc[hp][0][0][0];   // 256 f4
        const float4* srce = (const float4*)&g_we[hp][0][0][0];   // 256 f4
        ((float4*)&s_wc[0][0][0])[tid] = srcc[tid];
        ((float4*)&s_we[0][0][0])[tid] = srce[tid];
    }
    __syncthreads();

    // ---- Compress (8x8 matvec), both parities packed as float2 ----------
    {
        const float4* wc40 = (const float4*)&s_wc[0][0][g * 8];  // stride 16 f4
        const float4* wc41 = (const float4*)&s_wc[1][0][g * 8];
        float4 fa0 = make_float4(fea[0][0], fea[0][1], fea[0][2], fea[0][3]);
        float4 fb0 = make_float4(fea[0][4], fea[0][5], fea[0][6], fea[0][7]);
        float4 fa1 = make_float4(fea[1][0], fea[1][1], fea[1][2], fea[1][3]);
        float4 fb1 = make_float4(fea[1][4], fea[1][5], fea[1][6], fea[1][7]);
        #pragma unroll
        for (int j = 0; j < 8; j++) {
            float4 wa0 = wc40[j * 16], wb0 = wc40[j * 16 + 1];
            float4 wa1 = wc41[j * 16], wb1 = wc41[j * 16 + 1];
            float a0 = wa0.x * fa0.x + wa0.y * fa0.y + wa0.z * fa0.z + wa0.w * fa0.w
                     + wb0.x * fb0.x + wb0.y * fb0.y + wb0.z * fb0.z + wb0.w * fb0.w;
            float a1 = wa1.x * fa1.x + wa1.y * fa1.y + wa1.z * fa1.z + wa1.w * fa1.w
                     + wb1.x * fb1.x + wb1.y * fb1.y + wb1.z * fb1.z + wb1.w * fb1.w;
            s_part[j][g][l] = make_float2(a0, a1);
        }
    }
    __syncthreads();

    // ---- Reduce partials over channel groups: warp j -> midf[j][*] -------
    {
        const int j = g;
        float sx = 0.0f, sy = 0.0f;
        #pragma unroll
        for (int gg = 0; gg < 8; gg++) {
            float2 p = s_part[j][gg][l];
            sx += p.x; sy += p.y;
        }
        s_midf[j][l] = make_float2(sx, sy);
    }
    __syncthreads();

    // ---- Expand + residual + contiguous float2 stores -------------------
    float mid0[8], mid1[8];
    #pragma unroll
    for (int j = 0; j < 8; j++) {
        float2 mv = s_midf[j][l];
        mid0[j] = mv.x;
        mid1[j] = mv.y;
    }
    float* obp = out + ((size_t)(b * C_ + g * 8) * HHR_ + h) * WHR_ + 2 * m;
    #pragma unroll
    for (int i = 0; i < 8; i++) {
        const float4* we0 = (const float4*)&s_we[0][g * 8 + i][0];
        const float4* we1 = (const float4*)&s_we[1][g * 8 + i][0];
        float4 ea0 = we0[0], eb0 = we0[1];
        float4 ea1 = we1[0], eb1 = we1[1];
        float r0 = fea[0][i]
                 + ea0.x * mid0[0] + ea0.y * mid0[1] + ea0.z * mid0[2] + ea0.w * mid0[3]
                 + eb0.x * mid0[4] + eb0.y * mid0[5] + eb0.z * mid0[6] + eb0.w * mid0[7];
        float r1 = fea[1][i]
                 + ea1.x * mid1[0] + ea1.y * mid1[1] + ea1.z * mid1[2] + ea1.w * mid1[3]
                 + eb1.x * mid1[4] + eb1.y * mid1[5] + eb1.z * mid1[6] + eb1.w * mid1[7];
        float2 rv = make_float2(r0, r1);
        *(float2*)(obp + (size_t)i * HWHR_) = rv;
    }
}

// ---------------------------------------------------------------------------
extern "C" void kernel_launch(void* const* d_in, const int* in_sizes, int n_in,
                              void* d_out, int out_size)
{
    const float* fused = (const float*)d_in[1];
    const float* WC    = (const float*)d_in[2];
    const float* WE    = (const float*)d_in[3];
    const float* w1    = (const float*)d_in[4];
    const float* b1    = (const float*)d_in[5];
    const float* w2    = (const float*)d_in[6];
    const float* b2    = (const float*)d_in[7];
    const float* rw    = (const float*)d_in[8];
    const float* rb    = (const float*)d_in[9];
    const float* ow    = (const float*)d_in[10];
    const float* obv   = (const float*)d_in[11];
    float* out = (float*)d_out;

    precompute_kernel<<<1, 1024>>>(w1, b1, w2, b2, rw, rb, ow, obv, WC, WE);

    dim3 grid(WHR_ / 64, HHR_, B_);
    upsample_main<<<grid, 256>>>(fused, out);
}